// round 6
// baseline (speedup 1.0000x reference)
#include <cuda_runtime.h>

// FF_AtoB, FF_BtoA: [N=4, K*K=121, H=256, W=256] float32; K=11, pad=5.
// Output: scalar float loss.
#define NB   4
#define HH   256
#define WW   256
#define KK   11
#define PAD  5
#define HW   (HH * WW)           // 65536
#define NPIX (NB * HH * WW)      // 262144

// Pass2 smem tile: 12 halo rows x 272 float4 slots, parity-split within a row:
//   halo col lc (ix = lc - PAD): even lc -> slot lc/2, odd lc -> 136 + lc/2.
#define SROW 272
#define SM_ELEMS (12 * SROW)
#define SM_BYTES (SM_ELEMS * 16)   // 52224

// m1 packed per pixel: (m1A.x, m1A.y, m1B.x, m1B.y). 4 MB, L2-resident.
__device__ float4 g_m1[NPIX];
__device__ float  g_part[512];

// ---------------- Pass 1: explicit 22-deep load batching per dy ----------------
__global__ __launch_bounds__(256, 3) void pass1_kernel(
    const float* __restrict__ ffA, const float* __restrict__ ffB)
{
    const int tid = threadIdx.x;
    const int b   = blockIdx.x;
    const int n   = b >> 7;
    const int h   = ((b & 127) << 1) + (tid >> 7);
    const int wb  = (tid & 127) << 1;
    const float inv = 1.0f / 255.0f;

    float gxv[12], cf[12];
#pragma unroll
    for (int t = 0; t < 12; ++t) {
        int ix = wb + t - PAD;
        bool v = (unsigned)ix < (unsigned)WW;
        gxv[t] = v ? (float)ix * inv : 0.0f;
        cf[t]  = v ? 1.0f : 0.0f;
    }

    float m1ax[2] = {0,0}, m1ay[2] = {0,0};
    float m1bx[2] = {0,0}, m1by[2] = {0,0};

    const size_t base = (size_t)n * (121 * HW) + (size_t)h * WW + wb;

#pragma unroll 1
    for (int dy = 0; dy < KK; ++dy) {
        const int  iy  = h + dy - PAD;
        const bool rv  = (unsigned)iy < (unsigned)HH;
        const float rf  = rv ? 1.0f : 0.0f;
        const float gy0 = rv ? (float)iy * inv : 0.0f;
        const size_t rowbase = base + (size_t)(dy * KK) * HW;

        // Batch ALL loads for this dy before any FMA (forces 22-deep MLP).
        float2 a2[KK], b2[KK];
#pragma unroll
        for (int dx = 0; dx < KK; ++dx) {
            a2[dx] = __ldcs(reinterpret_cast<const float2*>(ffA + rowbase + (size_t)dx * HW));
            b2[dx] = __ldcs(reinterpret_cast<const float2*>(ffB + rowbase + (size_t)dx * HW));
        }

#pragma unroll
        for (int dx = 0; dx < KK; ++dx) {
            const float av[2] = {a2[dx].x, a2[dx].y};
            const float bv[2] = {b2[dx].x, b2[dx].y};
#pragma unroll
            for (int px = 0; px < 2; ++px) {
                const float xv = gxv[dx + px] * rf;
                const float yv = cf[dx + px] * gy0;
                m1ax[px] += av[px] * xv;
                m1ay[px] += av[px] * yv;
                m1bx[px] += bv[px] * xv;
                m1by[px] += bv[px] * yv;
            }
        }
    }

    const int o = (n * HH + h) * WW + wb;
#pragma unroll
    for (int px = 0; px < 2; ++px)
        g_m1[o + px] = make_float4(m1ax[px], m1ay[px], m1bx[px], m1by[px]);
}

// ---------------- Pass 2: fused dirs, parity-split smem, batched FF loads ------
// m2_ABA = filter(m1A, FF_BtoA);  m2_BAB = filter(m1B, FF_AtoB)
__global__ __launch_bounds__(256, 2) void pass2_kernel(
    const float* __restrict__ ffA, const float* __restrict__ ffB)
{
    extern __shared__ float4 sm[];   // [12][SROW]: even cols [0,136), odd [136,272)

    const int tid = threadIdx.x;
    const int b   = blockIdx.x;
    const int n   = b >> 7;
    const int h0  = (b & 127) << 1;
    const float inv = 1.0f / 255.0f;

    // Cooperative halo fill (parity-split).
    const int m1base = n * HW;
#pragma unroll 1
    for (int idx = tid; idx < SM_ELEMS; idx += 256) {
        const int r  = idx / SROW;
        const int s  = idx - r * SROW;
        const int p  = (s >= 136) ? 1 : 0;
        const int ci = s - p * 136;
        const int lc = 2 * ci + p;
        const int ix = lc - PAD;
        const int iy = h0 - PAD + r;
        float4 v = make_float4(0.0f, 0.0f, 0.0f, 0.0f);
        if ((unsigned)iy < (unsigned)HH && (unsigned)ix < (unsigned)WW)
            v = g_m1[m1base + iy * WW + ix];
        sm[idx] = v;
    }
    __syncthreads();

    const int ty = tid >> 7;
    const int h  = h0 + ty;
    const int i  = tid & 127;
    const int wb = i << 1;

    float m2ax[2] = {0,0}, m2ay[2] = {0,0};
    float m2bx[2] = {0,0}, m2by[2] = {0,0};

    const size_t base = (size_t)n * (121 * HW) + (size_t)h * WW + wb;

#pragma unroll 1
    for (int dy = 0; dy < KK; ++dy) {
        const size_t rowbase = base + (size_t)(dy * KK) * HW;

        // Batch global FF loads first (22-deep MLP) ...
        float2 a2[KK], b2[KK];
#pragma unroll
        for (int dx = 0; dx < KK; ++dx) {
            a2[dx] = __ldcs(reinterpret_cast<const float2*>(ffA + rowbase + (size_t)dx * HW));
            b2[dx] = __ldcs(reinterpret_cast<const float2*>(ffB + rowbase + (size_t)dx * HW));
        }

        // ... then the conflict-free smem window (LDS latency hidden by loads above).
        const float4* se = sm + (ty + dy) * SROW;
        float4 w[12];
#pragma unroll
        for (int t = 0; t < 12; ++t) {
            const int off = (t & 1) ? (136 + i + ((t - 1) >> 1)) : (i + (t >> 1));
            w[t] = se[off];
        }

#pragma unroll
        for (int dx = 0; dx < KK; ++dx) {
            const float av[2] = {a2[dx].x, a2[dx].y};
            const float bv[2] = {b2[dx].x, b2[dx].y};
#pragma unroll
            for (int px = 0; px < 2; ++px) {
                const float4 m = w[dx + px];
                m2ax[px] += bv[px] * m.x;   // ABA: weights ffB, data m1A
                m2ay[px] += bv[px] * m.y;
                m2bx[px] += av[px] * m.z;   // BAB: weights ffA, data m1B
                m2by[px] += av[px] * m.w;
            }
        }
    }

    const float gy = (float)h * inv;
    float acc = 0.0f;
#pragma unroll
    for (int px = 0; px < 2; ++px) {
        const float gx = (float)(wb + px) * inv;
        const float dax = gx - m2ax[px], day = gy - m2ay[px];
        const float dbx = gx - m2bx[px], dby = gy - m2by[px];
        acc += sqrtf(dax * dax + day * day) + sqrtf(dbx * dbx + dby * dby);
    }

#pragma unroll
    for (int off = 16; off > 0; off >>= 1)
        acc += __shfl_down_sync(0xffffffffu, acc, off);
    __shared__ float sred[8];
    if ((tid & 31) == 0) sred[tid >> 5] = acc;
    __syncthreads();
    if (tid == 0) {
        float t = 0.0f;
#pragma unroll
        for (int k = 0; k < 8; ++k) t += sred[k];
        g_part[blockIdx.x] = t;
    }
}

__global__ __launch_bounds__(512) void reduce_kernel(float* __restrict__ out)
{
    const int t = threadIdx.x;
    float v = g_part[t];
#pragma unroll
    for (int off = 16; off > 0; off >>= 1)
        v += __shfl_down_sync(0xffffffffu, v, off);
    __shared__ float s[16];
    if ((t & 31) == 0) s[t >> 5] = v;
    __syncthreads();
    if (t == 0) {
        float tot = 0.0f;
#pragma unroll
        for (int k = 0; k < 16; ++k) tot += s[k];
        out[0] = tot * (1.0f / (float)NPIX);
    }
}

extern "C" void kernel_launch(void* const* d_in, const int* in_sizes, int n_in,
                              void* d_out, int out_size)
{
    (void)in_sizes; (void)n_in; (void)out_size;
    const float* ffA = (const float*)d_in[0];
    const float* ffB = (const float*)d_in[1];
    float* out = (float*)d_out;

    cudaFuncSetAttribute(pass2_kernel,
                         cudaFuncAttributeMaxDynamicSharedMemorySize, SM_BYTES);

    pass1_kernel<<<512, 256>>>(ffA, ffB);
    pass2_kernel<<<512, 256, SM_BYTES>>>(ffA, ffB);
    reduce_kernel<<<1, 512>>>(out);
}

// round 7
// speedup vs baseline: 1.1517x; 1.1517x over previous
#include <cuda_runtime.h>

// FF_AtoB, FF_BtoA: [N=4, K*K=121, H=256, W=256] float32; K=11, pad=5.
// Output: scalar float loss.
#define NB   4
#define HH   256
#define WW   256
#define KK   11
#define PAD  5
#define HW   (HH * WW)           // 65536
#define NPIX (NB * HH * WW)      // 262144

// Pass2 smem tile: 12 halo rows x 272 float4 slots, parity-split within a row:
//   halo col lc (ix = lc - PAD): even lc -> slot lc/2, odd lc -> 136 + lc/2.
#define SROW 272
#define SM_ELEMS (12 * SROW)
#define SM_BYTES (SM_ELEMS * 16)   // 52224

// m1 packed per pixel: (m1A.x, m1A.y, m1B.x, m1B.y). 4 MB, L2-resident.
__device__ float4 g_m1[NPIX];
__device__ float  g_part[512];

// ---------------- Pass 1: R2 body, reg-capped to the known-good 64 ----------
__global__ __launch_bounds__(256, 4) void pass1_kernel(
    const float* __restrict__ ffA, const float* __restrict__ ffB)
{
    const int tid = threadIdx.x;
    const int b   = blockIdx.x;
    const int n   = b >> 7;
    const int h   = ((b & 127) << 1) + (tid >> 7);
    const int wb  = (tid & 127) << 1;
    const float inv = 1.0f / 255.0f;

    float gxv[12], cf[12];
#pragma unroll
    for (int t = 0; t < 12; ++t) {
        int ix = wb + t - PAD;
        bool v = (unsigned)ix < (unsigned)WW;
        gxv[t] = v ? (float)ix * inv : 0.0f;
        cf[t]  = v ? 1.0f : 0.0f;
    }

    float m1ax[2] = {0,0}, m1ay[2] = {0,0};
    float m1bx[2] = {0,0}, m1by[2] = {0,0};

    const size_t base = (size_t)n * (121 * HW) + (size_t)h * WW + wb;

#pragma unroll 1
    for (int dy = 0; dy < KK; ++dy) {
        const int  iy  = h + dy - PAD;
        const bool rv  = (unsigned)iy < (unsigned)HH;
        const float rf  = rv ? 1.0f : 0.0f;
        const float gy0 = rv ? (float)iy * inv : 0.0f;
        const size_t rowbase = base + (size_t)(dy * KK) * HW;
#pragma unroll
        for (int dx = 0; dx < KK; ++dx) {
            const float2 a2 = *reinterpret_cast<const float2*>(ffA + rowbase + (size_t)dx * HW);
            const float2 b2 = *reinterpret_cast<const float2*>(ffB + rowbase + (size_t)dx * HW);
            const float av[2] = {a2.x, a2.y};
            const float bv[2] = {b2.x, b2.y};
#pragma unroll
            for (int px = 0; px < 2; ++px) {
                const float xv = gxv[dx + px] * rf;
                const float yv = cf[dx + px] * gy0;
                m1ax[px] += av[px] * xv;
                m1ay[px] += av[px] * yv;
                m1bx[px] += bv[px] * xv;
                m1by[px] += bv[px] * yv;
            }
        }
    }

    const int o = (n * HH + h) * WW + wb;
#pragma unroll
    for (int px = 0; px < 2; ++px)
        g_m1[o + px] = make_float4(m1ax[px], m1ay[px], m1bx[px], m1by[px]);
}

// ---------------- Pass 2: fused dirs + parity-split smem (R5 config) --------
// m2_ABA = filter(m1A, FF_BtoA);  m2_BAB = filter(m1B, FF_AtoB)
__global__ __launch_bounds__(256, 2) void pass2_kernel(
    const float* __restrict__ ffA, const float* __restrict__ ffB)
{
    extern __shared__ float4 sm[];   // [12][SROW]: even cols [0,136), odd [136,272)

    const int tid = threadIdx.x;
    const int b   = blockIdx.x;
    const int n   = b >> 7;
    const int h0  = (b & 127) << 1;
    const float inv = 1.0f / 255.0f;

    // Cooperative halo fill (parity-split).
    const int m1base = n * HW;
#pragma unroll 1
    for (int idx = tid; idx < SM_ELEMS; idx += 256) {
        const int r  = idx / SROW;
        const int s  = idx - r * SROW;
        const int p  = (s >= 136) ? 1 : 0;
        const int ci = s - p * 136;
        const int lc = 2 * ci + p;
        const int ix = lc - PAD;
        const int iy = h0 - PAD + r;
        float4 v = make_float4(0.0f, 0.0f, 0.0f, 0.0f);
        if ((unsigned)iy < (unsigned)HH && (unsigned)ix < (unsigned)WW)
            v = g_m1[m1base + iy * WW + ix];
        sm[idx] = v;
    }
    __syncthreads();

    const int ty = tid >> 7;
    const int h  = h0 + ty;
    const int i  = tid & 127;
    const int wb = i << 1;

    float m2ax[2] = {0,0}, m2ay[2] = {0,0};
    float m2bx[2] = {0,0}, m2by[2] = {0,0};

    const size_t base = (size_t)n * (121 * HW) + (size_t)h * WW + wb;

#pragma unroll 1
    for (int dy = 0; dy < KK; ++dy) {
        const float4* se = sm + (ty + dy) * SROW;
        // Window: lc = 2i + t; conflict-free parity reads.
        float4 w[12];
#pragma unroll
        for (int t = 0; t < 12; ++t) {
            const int off = (t & 1) ? (136 + i + ((t - 1) >> 1)) : (i + (t >> 1));
            w[t] = se[off];
        }

        const size_t rowbase = base + (size_t)(dy * KK) * HW;
#pragma unroll
        for (int dx = 0; dx < KK; ++dx) {
            const float2 a2 = *reinterpret_cast<const float2*>(ffA + rowbase + (size_t)dx * HW);
            const float2 b2 = *reinterpret_cast<const float2*>(ffB + rowbase + (size_t)dx * HW);
            const float av[2] = {a2.x, a2.y};
            const float bv[2] = {b2.x, b2.y};
#pragma unroll
            for (int px = 0; px < 2; ++px) {
                const float4 m = w[dx + px];
                m2ax[px] += bv[px] * m.x;   // ABA: weights ffB, data m1A
                m2ay[px] += bv[px] * m.y;
                m2bx[px] += av[px] * m.z;   // BAB: weights ffA, data m1B
                m2by[px] += av[px] * m.w;
            }
        }
    }

    const float gy = (float)h * inv;
    float acc = 0.0f;
#pragma unroll
    for (int px = 0; px < 2; ++px) {
        const float gx = (float)(wb + px) * inv;
        const float dax = gx - m2ax[px], day = gy - m2ay[px];
        const float dbx = gx - m2bx[px], dby = gy - m2by[px];
        acc += sqrtf(dax * dax + day * day) + sqrtf(dbx * dbx + dby * dby);
    }

#pragma unroll
    for (int off = 16; off > 0; off >>= 1)
        acc += __shfl_down_sync(0xffffffffu, acc, off);
    __shared__ float sred[8];
    if ((tid & 31) == 0) sred[tid >> 5] = acc;
    __syncthreads();
    if (tid == 0) {
        float t = 0.0f;
#pragma unroll
        for (int k = 0; k < 8; ++k) t += sred[k];
        g_part[blockIdx.x] = t;
    }
}

__global__ __launch_bounds__(512) void reduce_kernel(float* __restrict__ out)
{
    const int t = threadIdx.x;
    float v = g_part[t];
#pragma unroll
    for (int off = 16; off > 0; off >>= 1)
        v += __shfl_down_sync(0xffffffffu, v, off);
    __shared__ float s[16];
    if ((t & 31) == 0) s[t >> 5] = v;
    __syncthreads();
    if (t == 0) {
        float tot = 0.0f;
#pragma unroll
        for (int k = 0; k < 16; ++k) tot += s[k];
        out[0] = tot * (1.0f / (float)NPIX);
    }
}

extern "C" void kernel_launch(void* const* d_in, const int* in_sizes, int n_in,
                              void* d_out, int out_size)
{
    (void)in_sizes; (void)n_in; (void)out_size;
    const float* ffA = (const float*)d_in[0];
    const float* ffB = (const float*)d_in[1];
    float* out = (float*)d_out;

    cudaFuncSetAttribute(pass2_kernel,
                         cudaFuncAttributeMaxDynamicSharedMemorySize, SM_BYTES);

    pass1_kernel<<<512, 256>>>(ffA, ffB);
    pass2_kernel<<<512, 256, SM_BYTES>>>(ffA, ffB);
    reduce_kernel<<<1, 512>>>(out);
}